// round 1
// baseline (speedup 1.0000x reference)
#include <cuda_runtime.h>
#include <math.h>

// Problem constants (fixed for AdaptiveFrequencySelector_37469294690510)
#define D_ 1024
#define H_ 8
#define F_ 4096

// Scratch (no allocation allowed in kernel_launch): keys for (b,h,f) and per-(b,h) thresholds.
// B*H <= 64, B*F*H <= 262144 for B=8.
__device__ unsigned long long g_keys[64 * 4096];
__device__ unsigned long long g_thr[64];

// Monotone float -> uint mapping (order-preserving, including negatives)
__device__ __forceinline__ unsigned int f2ord(float f) {
    unsigned int u = __float_as_uint(f);
    return (u & 0x80000000u) ? ~u : (u | 0x80000000u);
}

// ---------------------------------------------------------------------------
// Kernel 1: scores[b,f,h] = sum_d |x[b,f,d]| * W[d,h] + b[h]  -> 64-bit keys
// Warp-per-row. W transposed into smem [h][d] so LDS.128 is conflict-free
// (lane stride = 16B). fp32 FMA accumulation + butterfly shfl reduce.
// ---------------------------------------------------------------------------
__global__ void __launch_bounds__(256) score_kernel(
    const float* __restrict__ x,
    const float* __restrict__ W,      // [D, H] row-major
    const float* __restrict__ bias,   // [H]
    int nrows)                        // B*F
{
    __shared__ float Wt[H_][D_];      // 32 KB, transposed

    // Cooperative transpose load of W (one-time per block)
    for (int i = threadIdx.x; i < D_ * H_; i += blockDim.x) {
        int d = i / H_;
        int h = i - d * H_;
        Wt[h][d] = W[i];
    }
    __syncthreads();

    const int warp = threadIdx.x >> 5;
    const int lane = threadIdx.x & 31;
    const int warpsPerBlock = blockDim.x >> 5;
    const int rowStart  = blockIdx.x * warpsPerBlock + warp;
    const int rowStride = gridDim.x * warpsPerBlock;

    for (int row = rowStart; row < nrows; row += rowStride) {
        const float4* __restrict__ xr = (const float4*)(x + (size_t)row * D_);

        float acc[H_];
#pragma unroll
        for (int h = 0; h < H_; h++) acc[h] = 0.0f;

#pragma unroll
        for (int j = 0; j < D_ / 128; j++) {
            const int d4 = lane + 32 * j;     // float4 index; element d = 4*d4
            float4 xv = xr[d4];               // coalesced 512B per warp
            float a0 = fabsf(xv.x), a1 = fabsf(xv.y);
            float a2 = fabsf(xv.z), a3 = fabsf(xv.w);
#pragma unroll
            for (int h = 0; h < H_; h++) {
                const float4 wv = *(const float4*)&Wt[h][4 * d4];
                acc[h] = fmaf(a0, wv.x, acc[h]);
                acc[h] = fmaf(a1, wv.y, acc[h]);
                acc[h] = fmaf(a2, wv.z, acc[h]);
                acc[h] = fmaf(a3, wv.w, acc[h]);
            }
        }

        // Warp butterfly reduce (all lanes end with the full sum)
#pragma unroll
        for (int off = 16; off; off >>= 1) {
#pragma unroll
            for (int h = 0; h < H_; h++)
                acc[h] += __shfl_xor_sync(0xffffffffu, acc[h], off);
        }

        if (lane == 0) {
            const int b = row / F_;
            const int f = row - b * F_;
            const unsigned int finv = 0xFFFFFFFFu - (unsigned int)f; // tie -> lower f wins
#pragma unroll
            for (int h = 0; h < H_; h++) {
                float s = acc[h] + bias[h];
                unsigned long long key =
                    ((unsigned long long)f2ord(s) << 32) | (unsigned long long)finv;
                g_keys[((size_t)(b * H_ + h)) * F_ + f] = key;
            }
        }
    }
}

// ---------------------------------------------------------------------------
// Kernel 2: per (b,h) block: bitonic sort 4096 keys descending in smem,
// threshold = sorted[k-1], k = max(1, int(F * (sigmoid(off)*0.3 + 0.15)))
// computed in double to match the numpy float64 trace-time constant.
// ---------------------------------------------------------------------------
__global__ void __launch_bounds__(512) topk_kernel(
    const float* __restrict__ sparsity_offset)
{
    __shared__ unsigned long long s[F_];   // 32 KB
    const int bh = blockIdx.x;             // b*H + h
    const int h  = bh & (H_ - 1);
    const unsigned long long* __restrict__ src = g_keys + (size_t)bh * F_;

    for (int i = threadIdx.x; i < F_; i += blockDim.x) s[i] = src[i];
    __syncthreads();

    // Bitonic sort, overall descending
    for (int size = 2; size <= F_; size <<= 1) {
        for (int stride = size >> 1; stride > 0; stride >>= 1) {
            for (int i = threadIdx.x; i < F_; i += blockDim.x) {
                int j = i ^ stride;
                if (j > i) {
                    unsigned long long a = s[i], c = s[j];
                    bool desc = ((i & size) == 0);
                    bool sw = desc ? (a < c) : (a > c);
                    if (sw) { s[i] = c; s[j] = a; }
                }
            }
            __syncthreads();
        }
    }

    if (threadIdx.x == 0) {
        double off = (double)sparsity_offset[h];
        double sp  = 1.0 / (1.0 + exp(-off)) * 0.3 + 0.15;
        int k = (int)((double)F_ * sp);     // trunc toward zero, sp > 0
        if (k < 1)  k = 1;
        if (k > F_) k = F_;
        g_thr[bh] = s[k - 1];               // all keys distinct -> exactly k selected
    }
}

// ---------------------------------------------------------------------------
// Kernel 3: block-per-row. mask[h] = key(b,h,f) >= thr(b,h); write mask and
// x_filtered = x * mask (head_dim = 128, so each float4 lies in one head).
// ---------------------------------------------------------------------------
__global__ void __launch_bounds__(256) filter_kernel(
    const float* __restrict__ x,
    float* __restrict__ xout,
    float* __restrict__ mask_out)     // may be null
{
    const int row = blockIdx.x;        // b*F + f
    const int b = row >> 12;           // F_ = 4096
    const int f = row & (F_ - 1);
    const int t = threadIdx.x;

    __shared__ float m[H_];
    if (t < H_) {
        unsigned long long key = g_keys[((size_t)(b * H_ + t)) * F_ + f];
        float mv = (key >= g_thr[b * H_ + t]) ? 1.0f : 0.0f;
        m[t] = mv;
        if (mask_out) mask_out[(size_t)row * H_ + t] = mv;
    }
    __syncthreads();

    const float mm = m[t >> 5];        // head = (4t)/128 = t/32
    const float4* __restrict__ xr = (const float4*)(x + (size_t)row * D_);
    float4* __restrict__ xo = (float4*)(xout + (size_t)row * D_);
    float4 v = xr[t];
    v.x *= mm; v.y *= mm; v.z *= mm; v.w *= mm;
    xo[t] = v;
}

// ---------------------------------------------------------------------------
extern "C" void kernel_launch(void* const* d_in, const int* in_sizes, int n_in,
                              void* d_out, int out_size)
{
    const float* x    = (const float*)d_in[0];  // (B,F,D)
    const float* W    = (const float*)d_in[1];  // (D,H)
    const float* bias = (const float*)d_in[2];  // (H)
    const float* soff = (const float*)d_in[3];  // (H)

    const int nrows = in_sizes[0] / D_;         // B*F
    const int B = nrows / F_;

    float* xout = (float*)d_out;
    float* mask_out = nullptr;
    long long need = (long long)nrows * D_ + (long long)nrows * H_;
    if ((long long)out_size >= need)
        mask_out = (float*)d_out + (size_t)nrows * D_;

    // 1) scores -> 64-bit keys
    score_kernel<<<1024, 256>>>(x, W, bias, nrows);
    // 2) per-(b,h) exact top-k threshold
    topk_kernel<<<B * H_, 512>>>(soff);
    // 3) mask + filtered output
    filter_kernel<<<nrows, 256>>>(x, xout, mask_out);
}

// round 2
// speedup vs baseline: 1.4148x; 1.4148x over previous
#include <cuda_runtime.h>
#include <math.h>

// Problem constants (fixed for AdaptiveFrequencySelector_37469294690510)
#define D_ 1024
#define H_ 8
#define F_ 4096

// Scratch: keys laid out [b][f][h] (contiguous 64B per row), thresholds per (b,h).
__device__ unsigned long long g_keys[8 * 4096 * 8];
__device__ unsigned long long g_thr[64];

// Monotone float -> uint mapping (order-preserving, including negatives)
__device__ __forceinline__ unsigned int f2ord(float f) {
    unsigned int u = __float_as_uint(f);
    return (u & 0x80000000u) ? ~u : (u | 0x80000000u);
}

__device__ __forceinline__ unsigned long long umax64(unsigned long long a, unsigned long long b) { return a > b ? a : b; }
__device__ __forceinline__ unsigned long long umin64(unsigned long long a, unsigned long long b) { return a < b ? a : b; }

// ---------------------------------------------------------------------------
// Kernel 1: scores[b,f,h] = sum_d |x[b,f,d]| * W[d,h] + b[h]  -> 64-bit keys.
// 4 rows per warp: each W element read from smem is reused for 4 rows,
// cutting LDS traffic 4x. Moderate unroll keeps regs < 128 for occupancy.
// ---------------------------------------------------------------------------
__global__ void __launch_bounds__(256, 2) score_kernel(
    const float* __restrict__ x,
    const float* __restrict__ W,      // [D, H] row-major
    const float* __restrict__ bias,   // [H]
    int nrows)                        // B*F
{
    __shared__ float Wt[H_][D_];      // 32 KB, transposed

    for (int i = threadIdx.x; i < D_ * H_; i += blockDim.x) {
        int d = i >> 3;
        int h = i & 7;
        Wt[h][d] = W[i];
    }
    __syncthreads();

    const int warp = threadIdx.x >> 5;
    const int lane = threadIdx.x & 31;
    const int gwarp = blockIdx.x * 8 + warp;
    const int row0 = gwarp * 4;            // 4 consecutive rows per warp
    if (row0 >= nrows) return;

    const float4* __restrict__ x0 = (const float4*)(x + (size_t)row0 * D_);
    const float4* __restrict__ x1 = x0 + (D_ / 4);
    const float4* __restrict__ x2 = x1 + (D_ / 4);
    const float4* __restrict__ x3 = x2 + (D_ / 4);

    float acc[4][H_];
#pragma unroll
    for (int r = 0; r < 4; r++)
#pragma unroll
        for (int h = 0; h < H_; h++) acc[r][h] = 0.0f;

#pragma unroll 2
    for (int j = 0; j < D_ / 128; j++) {
        const int d4 = lane + 32 * j;             // float4 index
        float4 xv0 = x0[d4];
        float4 xv1 = x1[d4];
        float4 xv2 = x2[d4];
        float4 xv3 = x3[d4];
        float a0x = fabsf(xv0.x), a0y = fabsf(xv0.y), a0z = fabsf(xv0.z), a0w = fabsf(xv0.w);
        float a1x = fabsf(xv1.x), a1y = fabsf(xv1.y), a1z = fabsf(xv1.z), a1w = fabsf(xv1.w);
        float a2x = fabsf(xv2.x), a2y = fabsf(xv2.y), a2z = fabsf(xv2.z), a2w = fabsf(xv2.w);
        float a3x = fabsf(xv3.x), a3y = fabsf(xv3.y), a3z = fabsf(xv3.z), a3w = fabsf(xv3.w);
#pragma unroll
        for (int h = 0; h < H_; h++) {
            const float4 wv = *(const float4*)&Wt[h][4 * d4];
            acc[0][h] = fmaf(a0x, wv.x, acc[0][h]);
            acc[0][h] = fmaf(a0y, wv.y, acc[0][h]);
            acc[0][h] = fmaf(a0z, wv.z, acc[0][h]);
            acc[0][h] = fmaf(a0w, wv.w, acc[0][h]);
            acc[1][h] = fmaf(a1x, wv.x, acc[1][h]);
            acc[1][h] = fmaf(a1y, wv.y, acc[1][h]);
            acc[1][h] = fmaf(a1z, wv.z, acc[1][h]);
            acc[1][h] = fmaf(a1w, wv.w, acc[1][h]);
            acc[2][h] = fmaf(a2x, wv.x, acc[2][h]);
            acc[2][h] = fmaf(a2y, wv.y, acc[2][h]);
            acc[2][h] = fmaf(a2z, wv.z, acc[2][h]);
            acc[2][h] = fmaf(a2w, wv.w, acc[2][h]);
            acc[3][h] = fmaf(a3x, wv.x, acc[3][h]);
            acc[3][h] = fmaf(a3y, wv.y, acc[3][h]);
            acc[3][h] = fmaf(a3z, wv.z, acc[3][h]);
            acc[3][h] = fmaf(a3w, wv.w, acc[3][h]);
        }
    }

    // Butterfly reduce: all lanes end with full sums
#pragma unroll
    for (int off = 16; off; off >>= 1) {
#pragma unroll
        for (int r = 0; r < 4; r++)
#pragma unroll
            for (int h = 0; h < H_; h++)
                acc[r][h] += __shfl_xor_sync(0xffffffffu, acc[r][h], off);
    }

    if (lane < 4) {
        const int r = lane;                 // lanes 0..3 each emit one row
        const int row = row0 + r;
        const int b = row / F_;
        const int f = row - b * F_;
        const unsigned int finv = 0xFFFFFFFFu - (unsigned int)f;
        unsigned long long* __restrict__ kout = g_keys + (size_t)row * H_;
#pragma unroll
        for (int h = 0; h < H_; h++) {
            float s = acc[r][h] + bias[h];
            kout[h] = ((unsigned long long)f2ord(s) << 32) | (unsigned long long)finv;
        }
    }
}

// ---------------------------------------------------------------------------
// Kernel 2: per (b,h) block: register/shfl bitonic sort of 4096 keys
// (descending), threshold = sorted[k-1].
// 1024 threads x 4 elements, i = warp*128 + j*32 + lane:
//   stride 1..16  -> shfl_xor within warp
//   stride 32,64  -> register swap within thread (j bits)
//   stride >=128  -> smem exchange (only 15 of 78 passes)
// ---------------------------------------------------------------------------
__global__ void __launch_bounds__(1024) topk_kernel(
    const float* __restrict__ sparsity_offset)
{
    __shared__ unsigned long long s[F_];   // 32 KB
    const int bh = blockIdx.x;
    const int b  = bh >> 3;
    const int h  = bh & (H_ - 1);
    const int lane = threadIdx.x & 31;
    const int warp = threadIdx.x >> 5;

    unsigned long long v[4];
#pragma unroll
    for (int j = 0; j < 4; j++) {
        int i = warp * 128 + j * 32 + lane;
        v[j] = g_keys[((size_t)b * F_ + i) * H_ + h];
    }

    for (int size = 2; size <= F_; size <<= 1) {
        for (int stride = size >> 1; stride; stride >>= 1) {
            if (stride >= 128) {
#pragma unroll
                for (int j = 0; j < 4; j++) {
                    int i = warp * 128 + j * 32 + lane;
                    s[i] = v[j];
                }
                __syncthreads();
#pragma unroll
                for (int j = 0; j < 4; j++) {
                    int i = warp * 128 + j * 32 + lane;
                    unsigned long long p = s[i ^ stride];
                    bool desc = ((i & size) == 0);
                    bool low  = ((i & stride) == 0);
                    v[j] = (low == desc) ? umax64(v[j], p) : umin64(v[j], p);
                }
                __syncthreads();
            } else if (stride >= 32) {
                const int jb = stride >> 5;   // 1 or 2
#pragma unroll
                for (int j = 0; j < 4; j++) {
                    if ((j & jb) == 0) {
                        int i = warp * 128 + j * 32 + lane;
                        bool desc = ((i & size) == 0);
                        unsigned long long lo = v[j], hi = v[j | jb];
                        unsigned long long mx = umax64(lo, hi), mn = umin64(lo, hi);
                        v[j]      = desc ? mx : mn;
                        v[j | jb] = desc ? mn : mx;
                    }
                }
            } else {
#pragma unroll
                for (int j = 0; j < 4; j++) {
                    int i = warp * 128 + j * 32 + lane;
                    unsigned long long p = __shfl_xor_sync(0xffffffffu, v[j], stride);
                    bool desc = ((i & size) == 0);
                    bool low  = ((lane & stride) == 0);
                    v[j] = (low == desc) ? umax64(v[j], p) : umin64(v[j], p);
                }
            }
        }
    }

    // k = max(1, int(F * (sigmoid(off)*0.3 + 0.15))) in float64, matching numpy
    double off = (double)sparsity_offset[h];
    double sp  = 1.0 / (1.0 + exp(-off)) * 0.3 + 0.15;
    int k = (int)((double)F_ * sp);
    if (k < 1)  k = 1;
    if (k > F_) k = F_;

#pragma unroll
    for (int j = 0; j < 4; j++) {
        int i = warp * 128 + j * 32 + lane;
        if (i == k - 1) g_thr[bh] = v[j];   // descending: exactly k keys >= this
    }
}

// ---------------------------------------------------------------------------
// Kernel 3: block-per-row. mask[h] = key(b,f,h) >= thr(b,h); write mask and
// x_filtered = x * mask (head_dim = 128 -> each float4 within one head).
// ---------------------------------------------------------------------------
__global__ void __launch_bounds__(256) filter_kernel(
    const float* __restrict__ x,
    float* __restrict__ xout,
    float* __restrict__ mask_out)     // may be null
{
    const int row = blockIdx.x;        // b*F + f
    const int b = row >> 12;           // F_ = 4096
    const int t = threadIdx.x;

    __shared__ float m[H_];
    if (t < H_) {
        unsigned long long key = g_keys[(size_t)row * H_ + t];   // coalesced 64B
        float mv = (key >= g_thr[b * H_ + t]) ? 1.0f : 0.0f;
        m[t] = mv;
        if (mask_out) mask_out[(size_t)row * H_ + t] = mv;
    }
    __syncthreads();

    const float mm = m[t >> 5];        // head = (4t)/128 = t/32
    const float4* __restrict__ xr = (const float4*)(x + (size_t)row * D_);
    float4* __restrict__ xo = (float4*)(xout + (size_t)row * D_);
    float4 vv = xr[t];
    vv.x *= mm; vv.y *= mm; vv.z *= mm; vv.w *= mm;
    xo[t] = vv;
}

// ---------------------------------------------------------------------------
extern "C" void kernel_launch(void* const* d_in, const int* in_sizes, int n_in,
                              void* d_out, int out_size)
{
    const float* x    = (const float*)d_in[0];  // (B,F,D)
    const float* W    = (const float*)d_in[1];  // (D,H)
    const float* bias = (const float*)d_in[2];  // (H)
    const float* soff = (const float*)d_in[3];  // (H)

    const int nrows = in_sizes[0] / D_;         // B*F
    const int B = nrows / F_;

    float* xout = (float*)d_out;
    float* mask_out = nullptr;
    long long need = (long long)nrows * D_ + (long long)nrows * H_;
    if ((long long)out_size >= need)
        mask_out = (float*)d_out + (size_t)nrows * D_;

    // 1) scores -> 64-bit keys (4 rows per warp, 8 warps per block)
    int nblocks = (nrows / 4 + 7) / 8;
    score_kernel<<<nblocks, 256>>>(x, W, bias, nrows);
    // 2) per-(b,h) exact top-k threshold (register/shfl bitonic)
    topk_kernel<<<B * H_, 1024>>>(soff);
    // 3) mask + filtered output
    filter_kernel<<<nrows, 256>>>(x, xout, mask_out);
}

// round 3
// speedup vs baseline: 2.2528x; 1.5924x over previous
#include <cuda_runtime.h>
#include <math.h>

#define D_ 1024
#define H_ 8
#define F_ 4096

// Scratch: keys laid out [b][f][h] (contiguous 64B per row), thresholds per (b,h).
__device__ unsigned long long g_keys[8 * 4096 * 8];
__device__ unsigned long long g_thr[64];

// Monotone float -> uint mapping (order-preserving, including negatives)
__device__ __forceinline__ unsigned int f2ord(float f) {
    unsigned int u = __float_as_uint(f);
    return (u & 0x80000000u) ? ~u : (u | 0x80000000u);
}

// ---------------------------------------------------------------------------
// Kernel 1: scores[b,f,h] = sum_d |x[b,f,d]| * W[d,h] + b[h]  -> 64-bit keys.
// 4 rows per warp (W smem reuse x4). Single-step prefetch keeps regs ~84 so
// 3 blocks/SM fit (launch_bounds(256,3)) -> 24 warps/SM.
// ---------------------------------------------------------------------------
__global__ void __launch_bounds__(256, 3) score_kernel(
    const float* __restrict__ x,
    const float* __restrict__ W,      // [D, H] row-major
    const float* __restrict__ bias,   // [H]
    int nrows)                        // B*F
{
    __shared__ float Wt[H_][D_];      // 32 KB, transposed

    for (int i = threadIdx.x; i < D_ * H_; i += blockDim.x) {
        int d = i >> 3;
        int h = i & 7;
        Wt[h][d] = W[i];
    }
    __syncthreads();

    const int warp = threadIdx.x >> 5;
    const int lane = threadIdx.x & 31;
    const int gwarp = blockIdx.x * 8 + warp;
    const int row0 = gwarp * 4;            // 4 consecutive rows per warp
    if (row0 >= nrows) return;

    const float4* __restrict__ x0 = (const float4*)(x + (size_t)row0 * D_);
    const float4* __restrict__ x1 = x0 + (D_ / 4);
    const float4* __restrict__ x2 = x1 + (D_ / 4);
    const float4* __restrict__ x3 = x2 + (D_ / 4);

    float acc[4][H_];
#pragma unroll
    for (int r = 0; r < 4; r++)
#pragma unroll
        for (int h = 0; h < H_; h++) acc[r][h] = 0.0f;

    // Prefetch first chunk
    float4 c0 = x0[lane], c1 = x1[lane], c2 = x2[lane], c3 = x3[lane];

#pragma unroll
    for (int j = 0; j < D_ / 128; j++) {
        float4 n0, n1, n2, n3;
        if (j < D_ / 128 - 1) {
            const int d4n = lane + 32 * (j + 1);
            n0 = x0[d4n]; n1 = x1[d4n]; n2 = x2[d4n]; n3 = x3[d4n];
        }
        const int d4 = lane + 32 * j;
        float a0x = fabsf(c0.x), a0y = fabsf(c0.y), a0z = fabsf(c0.z), a0w = fabsf(c0.w);
        float a1x = fabsf(c1.x), a1y = fabsf(c1.y), a1z = fabsf(c1.z), a1w = fabsf(c1.w);
        float a2x = fabsf(c2.x), a2y = fabsf(c2.y), a2z = fabsf(c2.z), a2w = fabsf(c2.w);
        float a3x = fabsf(c3.x), a3y = fabsf(c3.y), a3z = fabsf(c3.z), a3w = fabsf(c3.w);
#pragma unroll
        for (int h = 0; h < H_; h++) {
            const float4 wv = *(const float4*)&Wt[h][4 * d4];
            acc[0][h] = fmaf(a0x, wv.x, acc[0][h]);
            acc[0][h] = fmaf(a0y, wv.y, acc[0][h]);
            acc[0][h] = fmaf(a0z, wv.z, acc[0][h]);
            acc[0][h] = fmaf(a0w, wv.w, acc[0][h]);
            acc[1][h] = fmaf(a1x, wv.x, acc[1][h]);
            acc[1][h] = fmaf(a1y, wv.y, acc[1][h]);
            acc[1][h] = fmaf(a1z, wv.z, acc[1][h]);
            acc[1][h] = fmaf(a1w, wv.w, acc[1][h]);
            acc[2][h] = fmaf(a2x, wv.x, acc[2][h]);
            acc[2][h] = fmaf(a2y, wv.y, acc[2][h]);
            acc[2][h] = fmaf(a2z, wv.z, acc[2][h]);
            acc[2][h] = fmaf(a2w, wv.w, acc[2][h]);
            acc[3][h] = fmaf(a3x, wv.x, acc[3][h]);
            acc[3][h] = fmaf(a3y, wv.y, acc[3][h]);
            acc[3][h] = fmaf(a3z, wv.z, acc[3][h]);
            acc[3][h] = fmaf(a3w, wv.w, acc[3][h]);
        }
        c0 = n0; c1 = n1; c2 = n2; c3 = n3;
    }

    // Butterfly reduce: all lanes end with full sums
#pragma unroll
    for (int off = 16; off; off >>= 1) {
#pragma unroll
        for (int r = 0; r < 4; r++)
#pragma unroll
            for (int h = 0; h < H_; h++)
                acc[r][h] += __shfl_xor_sync(0xffffffffu, acc[r][h], off);
    }

    if (lane < 4) {
        const int r = lane;
        const int row = row0 + r;
        const int b = row / F_;
        const int f = row - b * F_;
        const unsigned int finv = 0xFFFFFFFFu - (unsigned int)f; // tie -> lower f wins
        unsigned long long* __restrict__ kout = g_keys + (size_t)row * H_;
#pragma unroll
        for (int h = 0; h < H_; h++) {
            float s = acc[r][h] + bias[h];
            kout[h] = ((unsigned long long)f2ord(s) << 32) | (unsigned long long)finv;
        }
    }
}

// ---------------------------------------------------------------------------
// Kernel 2: per (b,h) block: exact radix-select (k-th largest of 4096 unique
// 64-bit keys) via 8 passes of 8-bit digits, keys resident in smem.
// ---------------------------------------------------------------------------
__global__ void __launch_bounds__(1024) topk_kernel(
    const float* __restrict__ sparsity_offset)
{
    __shared__ unsigned long long s[F_];   // 32 KB
    __shared__ int hist[256];
    __shared__ int sh_bin, sh_need;

    const int bh = blockIdx.x;
    const int b  = bh >> 3;
    const int h  = bh & (H_ - 1);
    const int t  = threadIdx.x;
    const int lane = t & 31;

    // Load keys (stride-H in gmem; 8 sibling blocks share each 64B line via L2)
#pragma unroll
    for (int j = 0; j < 4; j++) {
        int i = t + j * 1024;
        s[i] = g_keys[((size_t)b * F_ + i) * H_ + h];
    }

    if (t == 0) {
        double off = (double)sparsity_offset[h];
        double sp  = 1.0 / (1.0 + exp(-off)) * 0.3 + 0.15;
        int k = (int)((double)F_ * sp);     // trunc, matches numpy int()
        if (k < 1)  k = 1;
        if (k > F_) k = F_;
        sh_need = k;
    }
    __syncthreads();

    unsigned long long prefix = 0ull, pmask = 0ull;

    for (int shift = 56; shift >= 0; shift -= 8) {
        // zero histogram
        if (t < 256) hist[t] = 0;
        __syncthreads();
        // count digits among keys matching current prefix
#pragma unroll
        for (int j = 0; j < 4; j++) {
            unsigned long long key = s[t + j * 1024];
            if ((key & pmask) == prefix)
                atomicAdd(&hist[(int)((key >> shift) & 255ull)], 1);
        }
        __syncthreads();

        // warp 0: find digit bin such that (#keys with higher digit) < need <= (... + bin count)
        if (t < 32) {
            int c[8], lsum = 0;
#pragma unroll
            for (int q = 0; q < 8; q++) { c[q] = hist[lane * 8 + q]; lsum += c[q]; }
            // inclusive suffix-sum across lanes (toward higher lanes = higher bins)
            int ssum = lsum;
#pragma unroll
            for (int off = 1; off < 32; off <<= 1) {
                int o = __shfl_down_sync(0xffffffffu, ssum, off);
                if (lane + off < 32) ssum += o;
            }
            int above = ssum - lsum;       // keys with digit in higher lanes
            int need = sh_need;
            // within this lane, scan bins from high (q=7) to low
            int cum = above;
#pragma unroll
            for (int q = 7; q >= 0; q--) {
                int bin = lane * 8 + q;
                if (cum < need && need <= cum + c[q]) {
                    sh_bin = bin;
                    sh_need = need - cum;  // remaining within this bin
                }
                cum += c[q];
            }
        }
        __syncthreads();
        prefix |= ((unsigned long long)sh_bin) << shift;
        pmask  |= (255ull << shift);
        __syncthreads();
    }

    if (t == 0) g_thr[bh] = prefix;       // exactly the k-th largest key
}

// ---------------------------------------------------------------------------
// Kernel 3: block-per-row. mask[h] = key(b,f,h) >= thr(b,h). For mask==0 heads
// the warp skips the x read entirely (warp-uniform branch, ~70% of reads).
// ---------------------------------------------------------------------------
__global__ void __launch_bounds__(256) filter_kernel(
    const float* __restrict__ x,
    float* __restrict__ xout,
    float* __restrict__ mask_out)     // may be null
{
    const int row = blockIdx.x;        // b*F + f
    const int b = row >> 12;           // F_ = 4096
    const int t = threadIdx.x;

    __shared__ float m[H_];
    if (t < H_) {
        unsigned long long key = g_keys[(size_t)row * H_ + t];   // coalesced 64B
        float mv = (key >= g_thr[b * H_ + t]) ? 1.0f : 0.0f;
        m[t] = mv;
        if (mask_out) mask_out[(size_t)row * H_ + t] = mv;
    }
    __syncthreads();

    const float mm = m[t >> 5];        // head = (4t)/128 = t/32 (warp-uniform)
    float4* __restrict__ xo = (float4*)(xout + (size_t)row * D_);
    if (mm != 0.0f) {
        const float4* __restrict__ xr = (const float4*)(x + (size_t)row * D_);
        xo[t] = xr[t];                 // mask==1: copy through
    } else {
        xo[t] = make_float4(0.f, 0.f, 0.f, 0.f);
    }
}

// ---------------------------------------------------------------------------
extern "C" void kernel_launch(void* const* d_in, const int* in_sizes, int n_in,
                              void* d_out, int out_size)
{
    const float* x    = (const float*)d_in[0];  // (B,F,D)
    const float* W    = (const float*)d_in[1];  // (D,H)
    const float* bias = (const float*)d_in[2];  // (H)
    const float* soff = (const float*)d_in[3];  // (H)

    const int nrows = in_sizes[0] / D_;         // B*F
    const int B = nrows / F_;

    float* xout = (float*)d_out;
    float* mask_out = nullptr;
    long long need = (long long)nrows * D_ + (long long)nrows * H_;
    if ((long long)out_size >= need)
        mask_out = (float*)d_out + (size_t)nrows * D_;

    int nblocks = (nrows / 4 + 7) / 8;
    score_kernel<<<nblocks, 256>>>(x, W, bias, nrows);
    topk_kernel<<<B * H_, 1024>>>(soff);
    filter_kernel<<<nrows, 256>>>(x, xout, mask_out);
}

// round 4
// speedup vs baseline: 2.5017x; 1.1105x over previous
#include <cuda_runtime.h>
#include <math.h>

#define D_ 1024
#define H_ 8
#define F_ 4096

// Scratch: keys laid out [b][f][h] (contiguous 64B per row), thresholds per (b,h).
__device__ unsigned long long g_keys[8 * 4096 * 8];
__device__ unsigned long long g_thr[64];

// Monotone float -> uint mapping (order-preserving, including negatives)
__device__ __forceinline__ unsigned int f2ord(float f) {
    unsigned int u = __float_as_uint(f);
    return (u & 0x80000000u) ? ~u : (u | 0x80000000u);
}

// ---------------------------------------------------------------------------
// Kernel 1: scores[b,f,h] = sum_d |x[b,f,d]| * W[d,h] + b[h]  -> 64-bit keys.
// 8 rows per warp: each W LDS.128 is reused for 8 rows (LDS traffic = 4KB/row,
// equal to LDG traffic). abs applied once at load time. Loads batched 8-wide
// per j-iteration for MLP=8.
// ---------------------------------------------------------------------------
__global__ void __launch_bounds__(256, 2) score_kernel(
    const float* __restrict__ x,
    const float* __restrict__ W,      // [D, H] row-major
    const float* __restrict__ bias,   // [H]
    int nrows)                        // B*F
{
    __shared__ float Wt[H_][D_];      // 32 KB, transposed

    for (int i = threadIdx.x; i < D_ * H_; i += blockDim.x) {
        int d = i >> 3;
        int h = i & 7;
        Wt[h][d] = W[i];
    }
    __syncthreads();

    const int warp = threadIdx.x >> 5;
    const int lane = threadIdx.x & 31;
    const int gwarp = blockIdx.x * 8 + warp;
    const int row0 = gwarp * 8;            // 8 consecutive rows per warp
    if (row0 >= nrows) return;

    const float4* __restrict__ xr = (const float4*)(x + (size_t)row0 * D_);

    float acc[8][H_];
#pragma unroll
    for (int r = 0; r < 8; r++)
#pragma unroll
        for (int h = 0; h < H_; h++) acc[r][h] = 0.0f;

#pragma unroll
    for (int j = 0; j < D_ / 128; j++) {
        const int d4 = lane + 32 * j;
        // Batched loads: 8 independent LDG.128 in flight, abs applied on arrival
        float4 c[8];
#pragma unroll
        for (int r = 0; r < 8; r++) {
            float4 v = xr[r * (D_ / 4) + d4];
            c[r].x = fabsf(v.x); c[r].y = fabsf(v.y);
            c[r].z = fabsf(v.z); c[r].w = fabsf(v.w);
        }
#pragma unroll
        for (int h = 0; h < H_; h++) {
            const float4 wv = *(const float4*)&Wt[h][4 * d4];
#pragma unroll
            for (int r = 0; r < 8; r++) {
                acc[r][h] = fmaf(c[r].x, wv.x, acc[r][h]);
                acc[r][h] = fmaf(c[r].y, wv.y, acc[r][h]);
                acc[r][h] = fmaf(c[r].z, wv.z, acc[r][h]);
                acc[r][h] = fmaf(c[r].w, wv.w, acc[r][h]);
            }
        }
    }

    // Butterfly reduce: all lanes end with full sums
#pragma unroll
    for (int off = 16; off; off >>= 1) {
#pragma unroll
        for (int r = 0; r < 8; r++)
#pragma unroll
            for (int h = 0; h < H_; h++)
                acc[r][h] += __shfl_xor_sync(0xffffffffu, acc[r][h], off);
    }

    if (lane < 8) {
        const int r = lane;                 // lanes 0..7 each emit one row
        const int row = row0 + r;
        const int b = row / F_;
        const int f = row - b * F_;
        const unsigned int finv = 0xFFFFFFFFu - (unsigned int)f; // tie -> lower f wins
        unsigned long long* __restrict__ kout = g_keys + (size_t)row * H_;
#pragma unroll
        for (int h = 0; h < H_; h++) {
            float s = acc[r][h] + bias[h];
            kout[h] = ((unsigned long long)f2ord(s) << 32) | (unsigned long long)finv;
        }
    }
}

// ---------------------------------------------------------------------------
// Kernel 2: per (b,h) block: exact radix-select (k-th largest of 4096 unique
// 64-bit keys) via 8 passes of 8-bit digits, keys resident in smem.
// ---------------------------------------------------------------------------
__global__ void __launch_bounds__(1024) topk_kernel(
    const float* __restrict__ sparsity_offset)
{
    __shared__ unsigned long long s[F_];   // 32 KB
    __shared__ int hist[256];
    __shared__ int sh_bin, sh_need;

    const int bh = blockIdx.x;
    const int b  = bh >> 3;
    const int h  = bh & (H_ - 1);
    const int t  = threadIdx.x;
    const int lane = t & 31;

#pragma unroll
    for (int j = 0; j < 4; j++) {
        int i = t + j * 1024;
        s[i] = g_keys[((size_t)b * F_ + i) * H_ + h];
    }

    if (t == 0) {
        double off = (double)sparsity_offset[h];
        double sp  = 1.0 / (1.0 + exp(-off)) * 0.3 + 0.15;
        int k = (int)((double)F_ * sp);     // trunc, matches numpy int()
        if (k < 1)  k = 1;
        if (k > F_) k = F_;
        sh_need = k;
    }
    __syncthreads();

    unsigned long long prefix = 0ull, pmask = 0ull;

    for (int shift = 56; shift >= 0; shift -= 8) {
        if (t < 256) hist[t] = 0;
        __syncthreads();
#pragma unroll
        for (int j = 0; j < 4; j++) {
            unsigned long long key = s[t + j * 1024];
            if ((key & pmask) == prefix)
                atomicAdd(&hist[(int)((key >> shift) & 255ull)], 1);
        }
        __syncthreads();

        if (t < 32) {
            int c[8], lsum = 0;
#pragma unroll
            for (int q = 0; q < 8; q++) { c[q] = hist[lane * 8 + q]; lsum += c[q]; }
            int ssum = lsum;
#pragma unroll
            for (int off = 1; off < 32; off <<= 1) {
                int o = __shfl_down_sync(0xffffffffu, ssum, off);
                if (lane + off < 32) ssum += o;
            }
            int above = ssum - lsum;
            int need = sh_need;
            int cum = above;
#pragma unroll
            for (int q = 7; q >= 0; q--) {
                int bin = lane * 8 + q;
                if (cum < need && need <= cum + c[q]) {
                    sh_bin = bin;
                    sh_need = need - cum;
                }
                cum += c[q];
            }
        }
        __syncthreads();
        prefix |= ((unsigned long long)sh_bin) << shift;
        pmask  |= (255ull << shift);
        __syncthreads();
    }

    if (t == 0) g_thr[bh] = prefix;       // exactly the k-th largest key
}

// ---------------------------------------------------------------------------
// Kernel 3: warp-autonomous, grid-stride. Warp = one head of one row
// (head = warp id, 32 lanes x 16B = 512B = head_dim*4). Lane 0 fetches
// key+threshold, shfl-broadcast; masked-out heads skip the x read.
// ---------------------------------------------------------------------------
__global__ void __launch_bounds__(256) filter_kernel(
    const float* __restrict__ x,
    float* __restrict__ xout,
    float* __restrict__ mask_out,     // may be null
    int nrows)
{
    const int head = threadIdx.x >> 5;
    const int lane = threadIdx.x & 31;

    for (int row = blockIdx.x; row < nrows; row += gridDim.x) {
        const int b = row >> 12;           // F_ = 4096
        float mv = 0.0f;
        if (lane == 0) {
            unsigned long long key = g_keys[(size_t)row * H_ + head];
            mv = (key >= g_thr[b * H_ + head]) ? 1.0f : 0.0f;
            if (mask_out) mask_out[(size_t)row * H_ + head] = mv;
        }
        mv = __shfl_sync(0xffffffffu, mv, 0);

        const int t4 = head * 32 + lane;
        float4* __restrict__ xo = (float4*)(xout + (size_t)row * D_);
        if (mv != 0.0f) {
            const float4* __restrict__ xr = (const float4*)(x + (size_t)row * D_);
            xo[t4] = xr[t4];
        } else {
            xo[t4] = make_float4(0.f, 0.f, 0.f, 0.f);
        }
    }
}

// ---------------------------------------------------------------------------
extern "C" void kernel_launch(void* const* d_in, const int* in_sizes, int n_in,
                              void* d_out, int out_size)
{
    const float* x    = (const float*)d_in[0];  // (B,F,D)
    const float* W    = (const float*)d_in[1];  // (D,H)
    const float* bias = (const float*)d_in[2];  // (H)
    const float* soff = (const float*)d_in[3];  // (H)

    const int nrows = in_sizes[0] / D_;         // B*F
    const int B = nrows / F_;

    float* xout = (float*)d_out;
    float* mask_out = nullptr;
    long long need = (long long)nrows * D_ + (long long)nrows * H_;
    if ((long long)out_size >= need)
        mask_out = (float*)d_out + (size_t)nrows * D_;

    // 1) scores -> keys (8 rows/warp, 8 warps/block)
    int nblocks = (nrows / 8 + 7) / 8;
    score_kernel<<<nblocks, 256>>>(x, W, bias, nrows);
    // 2) exact per-(b,h) top-k threshold via radix-select
    topk_kernel<<<B * H_, 1024>>>(soff);
    // 3) mask + filtered output (warp-autonomous)
    filter_kernel<<<2048, 256>>>(x, xout, mask_out, nrows);
}

// round 5
// speedup vs baseline: 2.6182x; 1.0466x over previous
#include <cuda_runtime.h>
#include <math.h>

#define D_ 1024
#define H_ 8
#define F_ 4096
#define R_ 5   // rows per warp in score kernel

// Scratch: keys laid out [b][f][h] (contiguous 64B per row), thresholds per (b,h).
__device__ unsigned long long g_keys[8 * 4096 * 8];
__device__ unsigned long long g_thr[64];

// Monotone float -> uint mapping (order-preserving, including negatives)
__device__ __forceinline__ unsigned int f2ord(float f) {
    unsigned int u = __float_as_uint(f);
    return (u & 0x80000000u) ? ~u : (u | 0x80000000u);
}

// ---------------------------------------------------------------------------
// Kernel 1: scores[b,f,h] = sum_d |x[b,f,d]| * W[d,h] + b[h]  -> 64-bit keys.
// 5 rows per warp: LDS traffic 1.6KB/row vs 4KB/row LDG. ~80 regs so 3
// blocks/SM fit (24 warps) for latency hiding. Persistent grid-stride.
// ---------------------------------------------------------------------------
__global__ void __launch_bounds__(256, 3) score_kernel(
    const float* __restrict__ x,
    const float* __restrict__ W,      // [D, H] row-major
    const float* __restrict__ bias,   // [H]
    int nrows)                        // B*F
{
    __shared__ float Wt[H_][D_];      // 32 KB, transposed

    for (int i = threadIdx.x; i < D_ * H_; i += blockDim.x) {
        int d = i >> 3;
        int h = i & 7;
        Wt[h][d] = W[i];
    }
    __syncthreads();

    const int warp = threadIdx.x >> 5;
    const int lane = threadIdx.x & 31;
    const int totalWarps = gridDim.x * 8;
    const int nbatch = (nrows + R_ - 1) / R_;

    for (int batch = blockIdx.x * 8 + warp; batch < nbatch; batch += totalWarps) {
        const int row0 = batch * R_;
        const bool full = (row0 + R_ <= nrows);
        const float4* __restrict__ xr = (const float4*)(x + (size_t)row0 * D_);

        float acc[R_][H_];
#pragma unroll
        for (int r = 0; r < R_; r++)
#pragma unroll
            for (int h = 0; h < H_; h++) acc[r][h] = 0.0f;

        if (full) {
#pragma unroll
            for (int j = 0; j < D_ / 128; j++) {
                const int d4 = lane + 32 * j;
                float4 c[R_];
#pragma unroll
                for (int r = 0; r < R_; r++) {
                    float4 v = xr[r * (D_ / 4) + d4];
                    c[r].x = fabsf(v.x); c[r].y = fabsf(v.y);
                    c[r].z = fabsf(v.z); c[r].w = fabsf(v.w);
                }
#pragma unroll
                for (int h = 0; h < H_; h++) {
                    const float4 wv = *(const float4*)&Wt[h][4 * d4];
#pragma unroll
                    for (int r = 0; r < R_; r++) {
                        acc[r][h] = fmaf(c[r].x, wv.x, acc[r][h]);
                        acc[r][h] = fmaf(c[r].y, wv.y, acc[r][h]);
                        acc[r][h] = fmaf(c[r].z, wv.z, acc[r][h]);
                        acc[r][h] = fmaf(c[r].w, wv.w, acc[r][h]);
                    }
                }
            }
        } else {
            // one partial batch at the very end
#pragma unroll
            for (int j = 0; j < D_ / 128; j++) {
                const int d4 = lane + 32 * j;
                float4 c[R_];
#pragma unroll
                for (int r = 0; r < R_; r++) {
                    if (row0 + r < nrows) {
                        float4 v = xr[r * (D_ / 4) + d4];
                        c[r].x = fabsf(v.x); c[r].y = fabsf(v.y);
                        c[r].z = fabsf(v.z); c[r].w = fabsf(v.w);
                    } else {
                        c[r] = make_float4(0.f, 0.f, 0.f, 0.f);
                    }
                }
#pragma unroll
                for (int h = 0; h < H_; h++) {
                    const float4 wv = *(const float4*)&Wt[h][4 * d4];
#pragma unroll
                    for (int r = 0; r < R_; r++) {
                        acc[r][h] = fmaf(c[r].x, wv.x, acc[r][h]);
                        acc[r][h] = fmaf(c[r].y, wv.y, acc[r][h]);
                        acc[r][h] = fmaf(c[r].z, wv.z, acc[r][h]);
                        acc[r][h] = fmaf(c[r].w, wv.w, acc[r][h]);
                    }
                }
            }
        }

        // Butterfly reduce: all lanes end with full sums
#pragma unroll
        for (int off = 16; off; off >>= 1) {
#pragma unroll
            for (int r = 0; r < R_; r++)
#pragma unroll
                for (int h = 0; h < H_; h++)
                    acc[r][h] += __shfl_xor_sync(0xffffffffu, acc[r][h], off);
        }

        if (lane < R_) {
            const int r = lane;
            const int row = row0 + r;
            if (row < nrows) {
                const int b = row / F_;
                const int f = row - b * F_;
                const unsigned int finv = 0xFFFFFFFFu - (unsigned int)f; // tie -> lower f
                unsigned long long* __restrict__ kout = g_keys + (size_t)row * H_;
#pragma unroll
                for (int h = 0; h < H_; h++) {
                    float s = acc[r][h] + bias[h];
                    kout[h] = ((unsigned long long)f2ord(s) << 32) | (unsigned long long)finv;
                }
            }
        }
    }
}

// ---------------------------------------------------------------------------
// Kernel 2: per (b,h) block: exact radix-select (k-th largest of 4096 unique
// 64-bit keys) via 8 passes of 8-bit digits, keys resident in smem.
// ---------------------------------------------------------------------------
__global__ void __launch_bounds__(1024) topk_kernel(
    const float* __restrict__ sparsity_offset)
{
    __shared__ unsigned long long s[F_];   // 32 KB
    __shared__ int hist[256];
    __shared__ int sh_bin, sh_need;

    const int bh = blockIdx.x;
    const int b  = bh >> 3;
    const int h  = bh & (H_ - 1);
    const int t  = threadIdx.x;
    const int lane = t & 31;

#pragma unroll
    for (int j = 0; j < 4; j++) {
        int i = t + j * 1024;
        s[i] = g_keys[((size_t)b * F_ + i) * H_ + h];
    }

    if (t == 0) {
        double off = (double)sparsity_offset[h];
        double sp  = 1.0 / (1.0 + exp(-off)) * 0.3 + 0.15;
        int k = (int)((double)F_ * sp);     // trunc, matches numpy int()
        if (k < 1)  k = 1;
        if (k > F_) k = F_;
        sh_need = k;
    }
    __syncthreads();

    unsigned long long prefix = 0ull, pmask = 0ull;

    for (int shift = 56; shift >= 0; shift -= 8) {
        if (t < 256) hist[t] = 0;
        __syncthreads();
#pragma unroll
        for (int j = 0; j < 4; j++) {
            unsigned long long key = s[t + j * 1024];
            if ((key & pmask) == prefix)
                atomicAdd(&hist[(int)((key >> shift) & 255ull)], 1);
        }
        __syncthreads();

        if (t < 32) {
            int c[8], lsum = 0;
#pragma unroll
            for (int q = 0; q < 8; q++) { c[q] = hist[lane * 8 + q]; lsum += c[q]; }
            int ssum = lsum;
#pragma unroll
            for (int off = 1; off < 32; off <<= 1) {
                int o = __shfl_down_sync(0xffffffffu, ssum, off);
                if (lane + off < 32) ssum += o;
            }
            int above = ssum - lsum;
            int need = sh_need;
            int cum = above;
#pragma unroll
            for (int q = 7; q >= 0; q--) {
                int bin = lane * 8 + q;
                if (cum < need && need <= cum + c[q]) {
                    sh_bin = bin;
                    sh_need = need - cum;
                }
                cum += c[q];
            }
        }
        __syncthreads();
        prefix |= ((unsigned long long)sh_bin) << shift;
        pmask  |= (255ull << shift);
        __syncthreads();
    }

    if (t == 0) g_thr[bh] = prefix;       // exactly the k-th largest key
}

// ---------------------------------------------------------------------------
// Kernel 3: warp-autonomous, persistent grid-stride. Warp = one head of one
// row. Lane 0 fetches key+threshold, shfl-broadcast; masked-out heads skip
// the x read entirely (~70% of reads).
// ---------------------------------------------------------------------------
__global__ void __launch_bounds__(256) filter_kernel(
    const float* __restrict__ x,
    float* __restrict__ xout,
    float* __restrict__ mask_out,     // may be null
    int nrows)
{
    const int head = threadIdx.x >> 5;
    const int lane = threadIdx.x & 31;

    for (int row = blockIdx.x; row < nrows; row += gridDim.x) {
        const int b = row >> 12;           // F_ = 4096
        float mv = 0.0f;
        if (lane == 0) {
            unsigned long long key = g_keys[(size_t)row * H_ + head];
            mv = (key >= g_thr[b * H_ + head]) ? 1.0f : 0.0f;
            if (mask_out) mask_out[(size_t)row * H_ + head] = mv;
        }
        mv = __shfl_sync(0xffffffffu, mv, 0);

        const int t4 = head * 32 + lane;
        float4* __restrict__ xo = (float4*)(xout + (size_t)row * D_);
        if (mv != 0.0f) {
            const float4* __restrict__ xr = (const float4*)(x + (size_t)row * D_);
            xo[t4] = xr[t4];
        } else {
            xo[t4] = make_float4(0.f, 0.f, 0.f, 0.f);
        }
    }
}

// ---------------------------------------------------------------------------
extern "C" void kernel_launch(void* const* d_in, const int* in_sizes, int n_in,
                              void* d_out, int out_size)
{
    const float* x    = (const float*)d_in[0];  // (B,F,D)
    const float* W    = (const float*)d_in[1];  // (D,H)
    const float* bias = (const float*)d_in[2];  // (H)
    const float* soff = (const float*)d_in[3];  // (H)

    const int nrows = in_sizes[0] / D_;         // B*F
    const int B = nrows / F_;

    float* xout = (float*)d_out;
    float* mask_out = nullptr;
    long long need = (long long)nrows * D_ + (long long)nrows * H_;
    if ((long long)out_size >= need)
        mask_out = (float*)d_out + (size_t)nrows * D_;

    // 1) scores -> keys (5 rows/warp, persistent 3 blocks/SM)
    score_kernel<<<444, 256>>>(x, W, bias, nrows);
    // 2) exact per-(b,h) top-k threshold via radix-select
    topk_kernel<<<B * H_, 1024>>>(soff);
    // 3) mask + filtered output (warp-autonomous, persistent)
    filter_kernel<<<1184, 256>>>(x, xout, mask_out, nrows);
}

// round 6
// speedup vs baseline: 2.6267x; 1.0032x over previous
#include <cuda_runtime.h>
#include <math.h>

#define D_ 1024
#define H_ 8
#define F_ 4096
#define R_ 5    // rows per warp in score kernel
#define TILE_ 32 // rows per filter block

// Scratch: keys laid out [b][f][h] (contiguous 64B per row), thresholds per (b,h).
__device__ unsigned long long g_keys[8 * 4096 * 8];
__device__ unsigned long long g_thr[64];

// Monotone float -> uint mapping (order-preserving, including negatives)
__device__ __forceinline__ unsigned int f2ord(float f) {
    unsigned int u = __float_as_uint(f);
    return (u & 0x80000000u) ? ~u : (u | 0x80000000u);
}

__device__ __forceinline__ unsigned long long pack2(float lo, float hi) {
    unsigned long long p;
    asm("mov.b64 %0, {%1, %2};" : "=l"(p) : "f"(lo), "f"(hi));
    return p;
}
__device__ __forceinline__ void unpack2(unsigned long long p, float& lo, float& hi) {
    asm("mov.b64 {%0, %1}, %2;" : "=f"(lo), "=f"(hi) : "l"(p));
}
#define FMA2(acc, a, b) \
    asm("fma.rn.f32x2 %0, %1, %2, %0;" : "+l"(acc) : "l"(a), "l"(b))

// ---------------------------------------------------------------------------
// Kernel 1: scores[b,f,h] = sum_d |x[b,f,d]| * W[d,h] + b[h]  -> 64-bit keys.
// Packed f32x2 FMA (FFMA2): acc.lo accumulates even components, acc.hi odd;
// score = lo + hi. Halves FMA instruction count vs scalar FFMA.
// 5 rows/warp for W smem reuse; persistent grid-stride.
// ---------------------------------------------------------------------------
__global__ void __launch_bounds__(256, 2) score_kernel(
    const float* __restrict__ x,
    const float* __restrict__ W,      // [D, H] row-major
    const float* __restrict__ bias,   // [H]
    int nrows)                        // B*F
{
    __shared__ __align__(16) float Wt[H_][D_];   // 32 KB, transposed

    for (int i = threadIdx.x; i < D_ * H_; i += blockDim.x) {
        int d = i >> 3;
        int h = i & 7;
        Wt[h][d] = W[i];
    }
    __syncthreads();

    const int warp = threadIdx.x >> 5;
    const int lane = threadIdx.x & 31;
    const int totalWarps = gridDim.x * 8;
    const int nbatch = (nrows + R_ - 1) / R_;
    const unsigned long long ABS2 = 0x7FFFFFFF7FFFFFFFull;

    for (int batch = blockIdx.x * 8 + warp; batch < nbatch; batch += totalWarps) {
        const int row0 = batch * R_;
        const bool full = (row0 + R_ <= nrows);
        const float4* __restrict__ xr = (const float4*)(x + (size_t)row0 * D_);

        unsigned long long acc2[R_][H_];
#pragma unroll
        for (int r = 0; r < R_; r++)
#pragma unroll
            for (int h = 0; h < H_; h++) acc2[r][h] = 0ull;

#pragma unroll
        for (int j = 0; j < D_ / 128; j++) {
            const int d4 = lane + 32 * j;
            unsigned long long axy[R_], azw[R_];
#pragma unroll
            for (int r = 0; r < R_; r++) {
                float4 v;
                if (full || row0 + r < nrows) v = xr[r * (D_ / 4) + d4];
                else v = make_float4(0.f, 0.f, 0.f, 0.f);
                axy[r] = pack2(v.x, v.y) & ABS2;   // |x|,|y| packed
                azw[r] = pack2(v.z, v.w) & ABS2;   // |z|,|w| packed
            }
#pragma unroll
            for (int h = 0; h < H_; h++) {
                // (wx,wy) and (wz,ww) as native 64-bit pairs from one LDS.128
                const ulonglong2 wv = *(const ulonglong2*)&Wt[h][4 * d4];
#pragma unroll
                for (int r = 0; r < R_; r++) {
                    FMA2(acc2[r][h], axy[r], wv.x);
                    FMA2(acc2[r][h], azw[r], wv.y);
                }
            }
        }

        // Collapse packed halves, then butterfly reduce
        float acc[R_][H_];
#pragma unroll
        for (int r = 0; r < R_; r++)
#pragma unroll
            for (int h = 0; h < H_; h++) {
                float lo, hi;
                unpack2(acc2[r][h], lo, hi);
                acc[r][h] = lo + hi;
            }

#pragma unroll
        for (int off = 16; off; off >>= 1) {
#pragma unroll
            for (int r = 0; r < R_; r++)
#pragma unroll
                for (int h = 0; h < H_; h++)
                    acc[r][h] += __shfl_xor_sync(0xffffffffu, acc[r][h], off);
        }

        if (lane < R_) {
            const int r = lane;
            const int row = row0 + r;
            if (row < nrows) {
                const int b = row / F_;
                const int f = row - b * F_;
                const unsigned int finv = 0xFFFFFFFFu - (unsigned int)f; // tie -> lower f
                unsigned long long* __restrict__ kout = g_keys + (size_t)row * H_;
#pragma unroll
                for (int h = 0; h < H_; h++) {
                    float s = acc[r][h] + bias[h];
                    kout[h] = ((unsigned long long)f2ord(s) << 32) | (unsigned long long)finv;
                }
            }
        }
    }
}

// ---------------------------------------------------------------------------
// Kernel 2: per (b,h) block: exact radix-select (k-th largest of 4096 unique
// 64-bit keys) via 8 passes of 8-bit digits, keys resident in smem.
// ---------------------------------------------------------------------------
__global__ void __launch_bounds__(1024) topk_kernel(
    const float* __restrict__ sparsity_offset)
{
    __shared__ unsigned long long s[F_];   // 32 KB
    __shared__ int hist[256];
    __shared__ int sh_bin, sh_need;

    const int bh = blockIdx.x;
    const int b  = bh >> 3;
    const int h  = bh & (H_ - 1);
    const int t  = threadIdx.x;
    const int lane = t & 31;

#pragma unroll
    for (int j = 0; j < 4; j++) {
        int i = t + j * 1024;
        s[i] = g_keys[((size_t)b * F_ + i) * H_ + h];
    }

    if (t == 0) {
        double off = (double)sparsity_offset[h];
        double sp  = 1.0 / (1.0 + exp(-off)) * 0.3 + 0.15;
        int k = (int)((double)F_ * sp);     // trunc, matches numpy int()
        if (k < 1)  k = 1;
        if (k > F_) k = F_;
        sh_need = k;
    }
    __syncthreads();

    unsigned long long prefix = 0ull, pmask = 0ull;

    for (int shift = 56; shift >= 0; shift -= 8) {
        if (t < 256) hist[t] = 0;
        __syncthreads();
#pragma unroll
        for (int j = 0; j < 4; j++) {
            unsigned long long key = s[t + j * 1024];
            if ((key & pmask) == prefix)
                atomicAdd(&hist[(int)((key >> shift) & 255ull)], 1);
        }
        __syncthreads();

        if (t < 32) {
            int c[8], lsum = 0;
#pragma unroll
            for (int q = 0; q < 8; q++) { c[q] = hist[lane * 8 + q]; lsum += c[q]; }
            int ssum = lsum;
#pragma unroll
            for (int off = 1; off < 32; off <<= 1) {
                int o = __shfl_down_sync(0xffffffffu, ssum, off);
                if (lane + off < 32) ssum += o;
            }
            int above = ssum - lsum;
            int need = sh_need;
            int cum = above;
#pragma unroll
            for (int q = 7; q >= 0; q--) {
                int bin = lane * 8 + q;
                if (cum < need && need <= cum + c[q]) {
                    sh_bin = bin;
                    sh_need = need - cum;
                }
                cum += c[q];
            }
        }
        __syncthreads();
        prefix |= ((unsigned long long)sh_bin) << shift;
        pmask  |= (255ull << shift);
        __syncthreads();
    }

    if (t == 0) g_thr[bh] = prefix;       // exactly the k-th largest key
}

// ---------------------------------------------------------------------------
// Kernel 3: tile of 32 rows per block. Phase 1: one coalesced burst loads all
// 32x8 keys -> masks in smem (+mask_out). Phase 2: stream 32 rows, warp-
// uniform skip of reads for masked-out heads, unrolled for MLP.
// ---------------------------------------------------------------------------
__global__ void __launch_bounds__(256) filter_kernel(
    const float* __restrict__ x,
    float* __restrict__ xout,
    float* __restrict__ mask_out)     // may be null
{
    __shared__ float m[TILE_][H_];
    const int tile0 = blockIdx.x * TILE_;
    const int t = threadIdx.x;

    // Phase 1: 256 threads = 32 rows x 8 heads, fully coalesced
    {
        const int rl = t >> 3;
        const int hd = t & 7;
        const int row = tile0 + rl;
        const int b = row >> 12;                 // F_ = 4096
        unsigned long long key = g_keys[(size_t)row * H_ + hd];
        float mv = (key >= g_thr[b * H_ + hd]) ? 1.0f : 0.0f;
        m[rl][hd] = mv;
        if (mask_out) mask_out[(size_t)row * H_ + hd] = mv;
    }
    __syncthreads();

    const int head = t >> 5;                      // warp-uniform head
#pragma unroll 4
    for (int r = 0; r < TILE_; r++) {
        const int row = tile0 + r;
        float4* __restrict__ xo = (float4*)(xout + (size_t)row * D_);
        if (m[r][head] != 0.0f) {
            const float4* __restrict__ xr = (const float4*)(x + (size_t)row * D_);
            xo[t] = xr[t];
        } else {
            xo[t] = make_float4(0.f, 0.f, 0.f, 0.f);
        }
    }
}

// ---------------------------------------------------------------------------
extern "C" void kernel_launch(void* const* d_in, const int* in_sizes, int n_in,
                              void* d_out, int out_size)
{
    const float* x    = (const float*)d_in[0];  // (B,F,D)
    const float* W    = (const float*)d_in[1];  // (D,H)
    const float* bias = (const float*)d_in[2];  // (H)
    const float* soff = (const float*)d_in[3];  // (H)

    const int nrows = in_sizes[0] / D_;         // B*F
    const int B = nrows / F_;

    float* xout = (float*)d_out;
    float* mask_out = nullptr;
    long long need = (long long)nrows * D_ + (long long)nrows * H_;
    if ((long long)out_size >= need)
        mask_out = (float*)d_out + (size_t)nrows * D_;

    // 1) scores -> keys (FFMA2, 5 rows/warp, persistent)
    score_kernel<<<296, 256>>>(x, W, bias, nrows);
    // 2) exact per-(b,h) top-k threshold via radix-select
    topk_kernel<<<B * H_, 1024>>>(soff);
    // 3) mask + filtered output (32-row tiles)
    filter_kernel<<<nrows / TILE_, 256>>>(x, xout, mask_out);
}